// round 15
// baseline (speedup 1.0000x reference)
#include <cuda_runtime.h>
#include <cuda_fp16.h>
#include <cstdint>
#include <math.h>

// Problem dims
constexpr int B_ = 4, T_ = 2048, DM_ = 1024, H_ = 16, D_ = 64;
constexpr int NROWS = B_ * T_;           // 8192
constexpr int KP = 1024;                 // plain fp16 GEMM (no split)
constexpr int STATE_ELEMS = B_ * H_ * D_ * D_;

// ---------------- scratch (device globals; allocation-free) ----------------
__device__ float g_QKV[(size_t)NROWS * 3072];   // fused Q|K|V fp32
__device__ float g_alpha[NROWS * H_];
__device__ float g_beta[NROWS * H_];
__device__ float g_Sdump[STATE_ELEMS];
__device__ float g_Wab32[32 * DM_];
__device__ __half g_A2[(size_t)NROWS * KP];
__device__ __half g_Y2[(size_t)NROWS * KP];     // scan writes fp16 directly
__device__ __half g_Wqkv[(size_t)3072 * KP];    // rows: Wq|Wk|Wv output cols
__device__ __half g_Wto[(size_t)DM_ * KP];

// ---------------------------------------------------------------------------
// fp16 mma.sync GEMM: C[8192, N] = A[8192,1024]f16 @ B[N,1024]f16^T
// R15: CTA 64x128, 8 warps (2M x 4N), warp tile 32x32 (acc 32 regs -> ~78
// regs/thread -> 3 CTAs/SM, 24 warps, occ 37.5%). Kc=64, double-buffered
// cp.async. smem rows padded to 72 halves (144B), conflict-free (R4 pattern;
// B-side addressing unchanged, A-side wm span halved).
// Epilogue: col0 in [1024,2048) (K region of fused QKV GEMM) -> per-row L2
// normalize per head (64 cols = warp pair wn&~1). Output GEMM (grid.x=8)
// never hits this range.
// ---------------------------------------------------------------------------
__global__ __launch_bounds__(256, 3) void gemm_mma(const __half* __restrict__ A,
                                                   const __half* __restrict__ Bw,
                                                   float* __restrict__ C, int ldc) {
    extern __shared__ char sm[];
    const int tid = threadIdx.x;
    const int lane = tid & 31, wid = tid >> 5;
    const int wm = wid & 1, wn = wid >> 1;       // 2 x 4 warp grid
    const int row0 = blockIdx.y * 64;
    const int col0 = blockIdx.x * 128;

    uint32_t sb;
    asm("{ .reg .u64 t; cvta.to.shared.u64 t, %1; cvt.u32.u64 %0, t; }" : "=r"(sb) : "l"(sm));

    // per-stage: A 64*144 = 9216 B; B 128*144 = 18432 B; stage = 27648.
    constexpr uint32_t STG = 27648u;
    const uint32_t A_OFF[2] = {0u, STG};
    const uint32_t B_OFF[2] = {9216u, STG + 9216u};

    float acc[2][4][4];
#pragma unroll
    for (int i = 0; i < 2; ++i)
#pragma unroll
        for (int j = 0; j < 4; ++j)
#pragma unroll
            for (int q = 0; q < 4; ++q) acc[i][j][q] = 0.f;

    auto load_chunk = [&](int c, int buf) {
        const __half* gA = A + (size_t)row0 * KP + c * 64;
        uint32_t ab = sb + A_OFF[buf];
#pragma unroll
        for (int l = 0; l < 2; ++l) {            // 64 rows x 8 chunks = 512
            int idx = tid + (l << 8);
            int r = idx >> 3, s = idx & 7;
            uint32_t so = ab + (uint32_t)(r * 144 + s * 16);
            const void* gp = gA + (size_t)r * KP + s * 8;
            asm volatile("cp.async.cg.shared.global [%0], [%1], 16;" :: "r"(so), "l"(gp));
        }
        const __half* gB = Bw + (size_t)col0 * KP + c * 64;
        uint32_t bbx = sb + B_OFF[buf];
#pragma unroll
        for (int l = 0; l < 4; ++l) {            // 128 rows x 8 chunks = 1024
            int idx = tid + (l << 8);
            int n = idx >> 3, s = idx & 7;
            uint32_t so = bbx + (uint32_t)(n * 144 + s * 16);
            const void* gp = gB + (size_t)n * KP + s * 8;
            asm volatile("cp.async.cg.shared.global [%0], [%1], 16;" :: "r"(so), "l"(gp));
        }
        asm volatile("cp.async.commit_group;" ::: "memory");
    };

    // per-lane ldmatrix base offsets (halves); pad-72 (R4). A wm span = 32.
    const uint32_t a_base = (uint32_t)((wm * 32 + (lane & 15)) * 72 + ((lane >> 4) << 3));
    const uint32_t b_base = (uint32_t)((wn * 32 + (((lane >> 4) & 1) << 3) + (lane & 7)) * 72 +
                                       (((lane >> 3) & 1) << 3));

    load_chunk(0, 0);

    constexpr int NCH = KP / 64;  // 16
    for (int c = 0; c < NCH; ++c) {
        const int buf = c & 1;
        if (c + 1 < NCH) {
            load_chunk(c + 1, buf ^ 1);
            asm volatile("cp.async.wait_group 1;" ::: "memory");
        } else {
            asm volatile("cp.async.wait_group 0;" ::: "memory");
        }
        __syncthreads();

        const uint32_t ab = sb + A_OFF[buf];
        const uint32_t bbs = sb + B_OFF[buf];
#pragma unroll
        for (int ks = 0; ks < 4; ++ks) {
            uint32_t af[2][4];
#pragma unroll
            for (int mi = 0; mi < 2; ++mi) {
                uint32_t addr = ab + (a_base + (uint32_t)(mi * 16 * 72 + ks * 16)) * 2;
                asm volatile("ldmatrix.sync.aligned.m8n8.x4.shared.b16 {%0,%1,%2,%3}, [%4];"
                             : "=r"(af[mi][0]), "=r"(af[mi][1]), "=r"(af[mi][2]), "=r"(af[mi][3])
                             : "r"(addr));
            }
            uint32_t bf[4][2];
#pragma unroll
            for (int nb = 0; nb < 2; ++nb) {
                uint32_t addr = bbs + (b_base + (uint32_t)(nb * 16 * 72 + ks * 16)) * 2;
                asm volatile("ldmatrix.sync.aligned.m8n8.x4.shared.b16 {%0,%1,%2,%3}, [%4];"
                             : "=r"(bf[2 * nb][0]), "=r"(bf[2 * nb][1]),
                               "=r"(bf[2 * nb + 1][0]), "=r"(bf[2 * nb + 1][1])
                             : "r"(addr));
            }
#pragma unroll
            for (int mi = 0; mi < 2; ++mi)
#pragma unroll
                for (int ni = 0; ni < 4; ++ni) {
                    asm volatile(
                        "mma.sync.aligned.m16n8k16.row.col.f32.f16.f16.f32 "
                        "{%0,%1,%2,%3}, {%4,%5,%6,%7}, {%8,%9}, {%0,%1,%2,%3};"
                        : "+f"(acc[mi][ni][0]), "+f"(acc[mi][ni][1]),
                          "+f"(acc[mi][ni][2]), "+f"(acc[mi][ni][3])
                        : "r"(af[mi][0]), "r"(af[mi][1]), "r"(af[mi][2]), "r"(af[mi][3]),
                          "r"(bf[ni][0]), "r"(bf[ni][1]));
                }
        }
        __syncthreads();
    }

    const int rb = row0 + wm * 32 + (lane >> 2);
    const int cb = col0 + wn * 32 + (lane & 3) * 2;

    if (col0 >= 1024 && col0 < 2048) {
        // ---- fused K L2-normalize: head = 64 cols = warp pair (wn & ~1) ----
        float* sspart = (float*)(sm + 2 * STG);   // [4 wn][64 rows]
#pragma unroll
        for (int mi = 0; mi < 2; ++mi) {
            float s0 = 0.f, s1 = 0.f;
#pragma unroll
            for (int ni = 0; ni < 4; ++ni) {
                s0 = fmaf(acc[mi][ni][0], acc[mi][ni][0], s0);
                s0 = fmaf(acc[mi][ni][1], acc[mi][ni][1], s0);
                s1 = fmaf(acc[mi][ni][2], acc[mi][ni][2], s1);
                s1 = fmaf(acc[mi][ni][3], acc[mi][ni][3], s1);
            }
            s0 += __shfl_xor_sync(~0u, s0, 1);
            s0 += __shfl_xor_sync(~0u, s0, 2);
            s1 += __shfl_xor_sync(~0u, s1, 1);
            s1 += __shfl_xor_sync(~0u, s1, 2);
            if ((lane & 3) == 0) {
                int r0 = wm * 32 + mi * 16 + (lane >> 2);
                sspart[wn * 64 + r0] = s0;
                sspart[wn * 64 + r0 + 8] = s1;
            }
        }
        __syncthreads();
        const int base = (wn & 2) * 64;   // head's warp-pair base
#pragma unroll
        for (int mi = 0; mi < 2; ++mi) {
            int r0 = wm * 32 + mi * 16 + (lane >> 2);
            float ss0 = sspart[base + r0] + sspart[base + 64 + r0];
            float ss1 = sspart[base + r0 + 8] + sspart[base + 64 + r0 + 8];
            float inv0 = 1.f / fmaxf(sqrtf(ss0), 1e-12f);
            float inv1 = 1.f / fmaxf(sqrtf(ss1), 1e-12f);
#pragma unroll
            for (int ni = 0; ni < 4; ++ni) {
                int r = rb + mi * 16, cc = cb + ni * 8;
                *(float2*)(C + (size_t)r * ldc + cc) =
                    make_float2(acc[mi][ni][0] * inv0, acc[mi][ni][1] * inv0);
                *(float2*)(C + (size_t)(r + 8) * ldc + cc) =
                    make_float2(acc[mi][ni][2] * inv1, acc[mi][ni][3] * inv1);
            }
        }
    } else {
#pragma unroll
        for (int mi = 0; mi < 2; ++mi)
#pragma unroll
            for (int ni = 0; ni < 4; ++ni) {
                int r = rb + mi * 16, cc = cb + ni * 8;
                *(float2*)(C + (size_t)r * ldc + cc) =
                    make_float2(acc[mi][ni][0], acc[mi][ni][1]);
                *(float2*)(C + (size_t)(r + 8) * ldc + cc) =
                    make_float2(acc[mi][ni][2], acc[mi][ni][3]);
            }
    }
}

// ---------------------------------------------------------------------------
// fp32 -> fp16 flat cast
// ---------------------------------------------------------------------------
__global__ __launch_bounds__(256) void convert16(const float* __restrict__ in,
                                                 __half* __restrict__ out) {
    size_t i = (size_t)blockIdx.x * 256 + threadIdx.x;
    float4 v = ((const float4*)in)[i];
    __half2 a = __halves2half2(__float2half(v.x), __float2half(v.y));
    __half2 b = __halves2half2(__float2half(v.z), __float2half(v.w));
    __half2* o = (__half2*)out + i * 2;
    o[0] = a;
    o[1] = b;
}

// 4x W[1024][1024] fp32 -> Wt[n][1024] fp16 (transposed, K-major), one launch
__global__ __launch_bounds__(256) void transpose16x4(
    const float* __restrict__ W0, const float* __restrict__ W1,
    const float* __restrict__ W2, const float* __restrict__ W3,
    __half* __restrict__ o0, __half* __restrict__ o1,
    __half* __restrict__ o2, __half* __restrict__ o3) {
    const int z = blockIdx.z;
    const float* W = (z == 0) ? W0 : (z == 1) ? W1 : (z == 2) ? W2 : W3;
    __half* out = (z == 0) ? o0 : (z == 1) ? o1 : (z == 2) ? o2 : o3;
    __shared__ float s[32][33];
    const int tx = threadIdx.x & 31, ty = threadIdx.x >> 5;
    const int k0 = blockIdx.y << 5, n0 = blockIdx.x << 5;
#pragma unroll
    for (int r = 0; r < 32; r += 8)
        s[ty + r][tx] = W[(size_t)(k0 + ty + r) * 1024 + n0 + tx];
    __syncthreads();
#pragma unroll
    for (int r = 0; r < 32; r += 8) {
        const int n = n0 + ty + r, k = k0 + tx;
        out[(size_t)n * KP + k] = __float2half(s[tx][ty + r]);
    }
}

// Wa/Wb [1024][16] -> Wt32[32][1024] fp32
__global__ __launch_bounds__(256) void gates_prep32(const float* __restrict__ Wa,
                                                    const float* __restrict__ Wb,
                                                    float* __restrict__ out) {
    const int o = blockIdx.x;
    const float* W = (o < 16) ? Wa : Wb;
    const int h = o & 15;
    for (int k = threadIdx.x; k < 1024; k += 256)
        out[(size_t)o * 1024 + k] = W[k * 16 + h];
}

// ---------------------------------------------------------------------------
// Gates: logits = x @ Wt32^T, + bias, sigmoid. Block = 64 rows x 32 outputs.
// ---------------------------------------------------------------------------
__global__ __launch_bounds__(256) void gates64(const float* __restrict__ x,
                                               const float* __restrict__ Wt,
                                               const float* __restrict__ ba,
                                               const float* __restrict__ bb,
                                               float* __restrict__ alpha,
                                               float* __restrict__ beta) {
    __shared__ float xs[64][64];
    __shared__ float ws[32][65];
    const int tid = threadIdx.x;
    const int row0 = blockIdx.x * 64;
    const int rg = tid >> 5;
    const int o = tid & 31;

    float acc[8];
#pragma unroll
    for (int p = 0; p < 8; ++p) acc[p] = 0.f;

    for (int kc = 0; kc < 16; ++kc) {
        __syncthreads();
#pragma unroll
        for (int l = 0; l < 4; ++l) {
            int idx = tid + (l << 8);
            int r = idx >> 4, q = idx & 15;
            float4 v = *(const float4*)(x + (size_t)(row0 + r) * 1024 + kc * 64 + q * 4);
            *(float4*)(&xs[r][q * 4]) = v;
        }
#pragma unroll
        for (int l = 0; l < 2; ++l) {
            int idx = tid + (l << 8);
            int r = idx >> 4, q = idx & 15;
            float4 v = *(const float4*)(Wt + (size_t)r * 1024 + kc * 64 + q * 4);
            ws[r][q * 4 + 0] = v.x; ws[r][q * 4 + 1] = v.y;
            ws[r][q * 4 + 2] = v.z; ws[r][q * 4 + 3] = v.w;
        }
        __syncthreads();
#pragma unroll 8
        for (int k = 0; k < 64; ++k) {
            float wv = ws[o][k];
#pragma unroll
            for (int p = 0; p < 8; ++p)
                acc[p] = fmaf(xs[rg * 8 + p][k], wv, acc[p]);
        }
    }

    const float bias = (o < 16) ? ba[o] : bb[o - 16];
#pragma unroll
    for (int p = 0; p < 8; ++p) {
        float r = 1.f / (1.f + expf(-(acc[p] + bias)));
        int row = row0 + rg * 8 + p;
        if (o < 16) alpha[(size_t)row * 16 + o] = r;
        else        beta[(size_t)row * 16 + (o - 16)] = r;
    }
}

// ---------------------------------------------------------------------------
// Sequential scan v3: 128 blocks (one per (b,h,row-half)), 256 threads.
// Thread owns row i (of 32) and 8 cols; 8-lane xor-shfl reduction.
// Writes Y directly as fp16 into Y2.
// ---------------------------------------------------------------------------
__global__ __launch_bounds__(256) void scan_kernel3(
    const float* __restrict__ QKV, const float* __restrict__ alpha,
    const float* __restrict__ beta, const float* __restrict__ S0,
    __half* __restrict__ Y2, float* __restrict__ Sout) {
    constexpr int CH = 16;
    __shared__ float cq[2][CH][64];
    __shared__ float ck[2][CH][64];
    __shared__ float cv[2][CH][32];
    __shared__ float ca[2][CH];
    __shared__ float cb[2][CH];

    const int tid = threadIdx.x;
    const int bh2 = blockIdx.x;          // 0..127
    const int bh = bh2 >> 1, half = bh2 & 1;
    const int b = bh >> 4, h = bh & 15;
    const int i = tid >> 3;              // row 0..31
    const int gi = half * 32 + i;        // row 0..63
    const int jg = tid & 7;              // col group
    const int j0 = jg << 3;              // 8 cols

    float4 s4[2];
    {
        const float4* sp = (const float4*)(S0 + ((size_t)bh * 64 + gi) * 64 + j0);
        s4[0] = sp[0]; s4[1] = sp[1];
    }

    const float* rowQ = QKV + (size_t)b * T_ * 3072 + (size_t)h * 64;

    auto load_chunk = [&](int t0, int buf) {
        {
            int st = tid >> 4, f = (tid & 15) << 2;
            const float* base = rowQ + (size_t)(t0 + st) * 3072;
            *(float4*)(&cq[buf][st][f]) = *(const float4*)(base + f);
            *(float4*)(&ck[buf][st][f]) = *(const float4*)(base + 1024 + f);
        }
        if (tid < 128) {
            int st = tid >> 3, f = (tid & 7) << 2;
            const float* base = rowQ + (size_t)(t0 + st) * 3072 + 2048 + half * 32;
            *(float4*)(&cv[buf][st][f]) = *(const float4*)(base + f);
        }
        if (tid < CH)
            ca[buf][tid] = alpha[((size_t)b * T_ + t0 + tid) * H_ + h];
        else if (tid < 2 * CH)
            cb[buf][tid - CH] = beta[((size_t)b * T_ + t0 + tid - CH) * H_ + h];
    };

    const size_t ybase = (size_t)b * T_ * KP + (size_t)h * 64 + gi;
    const int nch = T_ / CH;
    load_chunk(0, 0);
    __syncthreads();

    for (int c = 0; c < nch; ++c) {
        const int buf = c & 1;
        if (c + 1 < nch) load_chunk((c + 1) * CH, buf ^ 1);

#pragma unroll 4
        for (int s = 0; s < CH; ++s) {
            const float a = ca[buf][s];
            const float bg = cb[buf][s];
            const float bv = bg * cv[buf][s][i];
            const float4* kp = (const float4*)(&ck[buf][s][j0]);
            const float4* qp = (const float4*)(&cq[buf][s][j0]);
            float partial = 0.f;
#pragma unroll
            for (int v = 0; v < 2; ++v) {
                float4 kk = kp[v];
                float4 qq = qp[v];
                s4[v].x = fmaf(a, s4[v].x, bv * kk.x); partial = fmaf(s4[v].x, qq.x, partial);
                s4[v].y = fmaf(a, s4[v].y, bv * kk.y); partial = fmaf(s4[v].y, qq.y, partial);
                s4[v].z = fmaf(a, s4[v].z, bv * kk.z); partial = fmaf(s4[v].z, qq.z, partial);
                s4[v].w = fmaf(a, s4[v].w, bv * kk.w); partial = fmaf(s4[v].w, qq.w, partial);
            }
            partial += __shfl_xor_sync(~0u, partial, 1);
            partial += __shfl_xor_sync(~0u, partial, 2);
            partial += __shfl_xor_sync(~0u, partial, 4);
            if (jg == 0)
                Y2[ybase + (size_t)(c * CH + s) * KP] = __float2half(partial);
        }
        __syncthreads();
    }

    float4* so = (float4*)(Sout + ((size_t)bh * 64 + gi) * 64 + j0);
    so[0] = s4[0]; so[1] = s4[1];
}

// ---------------------------------------------------------------------------
extern "C" void kernel_launch(void* const* d_in, const int* in_sizes, int n_in,
                              void* d_out, int out_size) {
    (void)in_sizes; (void)n_in;
    const float* x  = (const float*)d_in[0];
    const float* S0 = (const float*)d_in[1];
    const float* Wq = (const float*)d_in[2];
    const float* Wk = (const float*)d_in[3];
    const float* Wv = (const float*)d_in[4];
    const float* Wa = (const float*)d_in[5];
    const float* ba = (const float*)d_in[6];
    const float* Wb = (const float*)d_in[7];
    const float* bb = (const float*)d_in[8];
    const float* Wo = (const float*)d_in[9];
    float* out = (float*)d_out;

    float *QKVd, *al, *be, *Sdump, *Wab32;
    __half *A2, *Y2, *Wqkv, *Wto;
    cudaGetSymbolAddress((void**)&QKVd, g_QKV);
    cudaGetSymbolAddress((void**)&al, g_alpha);
    cudaGetSymbolAddress((void**)&be, g_beta);
    cudaGetSymbolAddress((void**)&Sdump, g_Sdump);
    cudaGetSymbolAddress((void**)&Wab32, g_Wab32);
    cudaGetSymbolAddress((void**)&A2, g_A2);
    cudaGetSymbolAddress((void**)&Y2, g_Y2);
    cudaGetSymbolAddress((void**)&Wqkv, g_Wqkv);
    cudaGetSymbolAddress((void**)&Wto, g_Wto);

    float* Sout = (out_size >= NROWS * DM_ + STATE_ELEMS) ? out + (size_t)NROWS * DM_ : Sdump;

    constexpr int GSMEM = 2 * 27648 + 4 * 64 * 4;   // stages + knorm partials = 56320
    cudaFuncSetAttribute(gemm_mma, cudaFuncAttributeMaxDynamicSharedMemorySize, GSMEM);

    convert16<<<NROWS, 256>>>(x, A2);
    transpose16x4<<<dim3(32, 32, 4), 256>>>(Wq, Wk, Wv, Wo,
                                            Wqkv,
                                            Wqkv + (size_t)1024 * KP,
                                            Wqkv + (size_t)2048 * KP,
                                            Wto);
    gates_prep32<<<32, 256>>>(Wa, Wb, Wab32);
    gemm_mma<<<dim3(3072 / 128, NROWS / 64), 256, GSMEM>>>(A2, Wqkv, QKVd, 3072);  // + fused knorm
    gates64<<<NROWS / 64, 256>>>(x, Wab32, ba, bb, al, be);
    scan_kernel3<<<128, 256>>>(QKVd, al, be, S0, Y2, Sout);
    gemm_mma<<<dim3(1024 / 128, NROWS / 64), 256, GSMEM>>>(Y2, Wto, out, 1024);
}

// round 16
// speedup vs baseline: 1.0048x; 1.0048x over previous
#include <cuda_runtime.h>
#include <cuda_fp16.h>
#include <cstdint>
#include <math.h>

// Problem dims
constexpr int B_ = 4, T_ = 2048, DM_ = 1024, H_ = 16, D_ = 64;
constexpr int NROWS = B_ * T_;           // 8192
constexpr int KP = 1024;                 // plain fp16 GEMM (no split)
constexpr int STATE_ELEMS = B_ * H_ * D_ * D_;

// ---------------- scratch (device globals; allocation-free) ----------------
__device__ float g_QKV[(size_t)NROWS * 3072];   // fused Q|K|V fp32
__device__ float g_alpha[NROWS * H_];
__device__ float g_beta[NROWS * H_];
__device__ float g_Sdump[STATE_ELEMS];
__device__ float g_Wab32[32 * DM_];
__device__ __half g_A2[(size_t)NROWS * KP];
__device__ __half g_Y2[(size_t)NROWS * KP];     // scan writes fp16 directly
__device__ __half g_Wqkv[(size_t)3072 * KP];    // rows: Wq|Wk|Wv output cols
__device__ __half g_Wto[(size_t)DM_ * KP];

// ---------------------------------------------------------------------------
// fp16 mma.sync GEMM — EXACT R14 config (proven 690.9us): CTA 128x128,
// 8 warps (2M x 4N), warp tile 64x32, Kc=64, double-buffered cp.async,
// 2 CTAs/SM, pad-72 smem. Fused K-normalize epilogue for col0 in [1024,2048).
// ---------------------------------------------------------------------------
__global__ __launch_bounds__(256, 2) void gemm_mma(const __half* __restrict__ A,
                                                   const __half* __restrict__ Bw,
                                                   float* __restrict__ C, int ldc) {
    extern __shared__ char sm[];
    const int tid = threadIdx.x;
    const int lane = tid & 31, wid = tid >> 5;
    const int wm = wid & 1, wn = wid >> 1;       // 2 x 4 warp grid
    const int row0 = blockIdx.y * 128;
    const int col0 = blockIdx.x * 128;

    uint32_t sb;
    asm("{ .reg .u64 t; cvta.to.shared.u64 t, %1; cvt.u32.u64 %0, t; }" : "=r"(sb) : "l"(sm));

    const uint32_t A_OFF[2] = {0u, 36864u};
    const uint32_t B_OFF[2] = {18432u, 36864u + 18432u};

    float acc[4][4][4];
#pragma unroll
    for (int i = 0; i < 4; ++i)
#pragma unroll
        for (int j = 0; j < 4; ++j)
#pragma unroll
            for (int q = 0; q < 4; ++q) acc[i][j][q] = 0.f;

    auto load_chunk = [&](int c, int buf) {
        const __half* gA = A + (size_t)row0 * KP + c * 64;
        uint32_t ab = sb + A_OFF[buf];
#pragma unroll
        for (int l = 0; l < 4; ++l) {
            int idx = tid + (l << 8);
            int r = idx >> 3, s = idx & 7;
            uint32_t so = ab + (uint32_t)(r * 144 + s * 16);
            const void* gp = gA + (size_t)r * KP + s * 8;
            asm volatile("cp.async.cg.shared.global [%0], [%1], 16;" :: "r"(so), "l"(gp));
        }
        const __half* gB = Bw + (size_t)col0 * KP + c * 64;
        uint32_t bbx = sb + B_OFF[buf];
#pragma unroll
        for (int l = 0; l < 4; ++l) {
            int idx = tid + (l << 8);
            int n = idx >> 3, s = idx & 7;
            uint32_t so = bbx + (uint32_t)(n * 144 + s * 16);
            const void* gp = gB + (size_t)n * KP + s * 8;
            asm volatile("cp.async.cg.shared.global [%0], [%1], 16;" :: "r"(so), "l"(gp));
        }
        asm volatile("cp.async.commit_group;" ::: "memory");
    };

    const uint32_t a_base = (uint32_t)((wm * 64 + (lane & 15)) * 72 + ((lane >> 4) << 3));
    const uint32_t b_base = (uint32_t)((wn * 32 + (((lane >> 4) & 1) << 3) + (lane & 7)) * 72 +
                                       (((lane >> 3) & 1) << 3));

    load_chunk(0, 0);

    constexpr int NCH = KP / 64;  // 16
    for (int c = 0; c < NCH; ++c) {
        const int buf = c & 1;
        if (c + 1 < NCH) {
            load_chunk(c + 1, buf ^ 1);
            asm volatile("cp.async.wait_group 1;" ::: "memory");
        } else {
            asm volatile("cp.async.wait_group 0;" ::: "memory");
        }
        __syncthreads();

        const uint32_t ab = sb + A_OFF[buf];
        const uint32_t bbs = sb + B_OFF[buf];
#pragma unroll
        for (int ks = 0; ks < 4; ++ks) {
            uint32_t af[4][4];
#pragma unroll
            for (int mi = 0; mi < 4; ++mi) {
                uint32_t addr = ab + (a_base + (uint32_t)(mi * 16 * 72 + ks * 16)) * 2;
                asm volatile("ldmatrix.sync.aligned.m8n8.x4.shared.b16 {%0,%1,%2,%3}, [%4];"
                             : "=r"(af[mi][0]), "=r"(af[mi][1]), "=r"(af[mi][2]), "=r"(af[mi][3])
                             : "r"(addr));
            }
            uint32_t bf[4][2];
#pragma unroll
            for (int nb = 0; nb < 2; ++nb) {
                uint32_t addr = bbs + (b_base + (uint32_t)(nb * 16 * 72 + ks * 16)) * 2;
                asm volatile("ldmatrix.sync.aligned.m8n8.x4.shared.b16 {%0,%1,%2,%3}, [%4];"
                             : "=r"(bf[2 * nb][0]), "=r"(bf[2 * nb][1]),
                               "=r"(bf[2 * nb + 1][0]), "=r"(bf[2 * nb + 1][1])
                             : "r"(addr));
            }
#pragma unroll
            for (int mi = 0; mi < 4; ++mi)
#pragma unroll
                for (int ni = 0; ni < 4; ++ni) {
                    asm volatile(
                        "mma.sync.aligned.m16n8k16.row.col.f32.f16.f16.f32 "
                        "{%0,%1,%2,%3}, {%4,%5,%6,%7}, {%8,%9}, {%0,%1,%2,%3};"
                        : "+f"(acc[mi][ni][0]), "+f"(acc[mi][ni][1]),
                          "+f"(acc[mi][ni][2]), "+f"(acc[mi][ni][3])
                        : "r"(af[mi][0]), "r"(af[mi][1]), "r"(af[mi][2]), "r"(af[mi][3]),
                          "r"(bf[ni][0]), "r"(bf[ni][1]));
                }
        }
        __syncthreads();
    }

    const int rb = row0 + wm * 64 + (lane >> 2);
    const int cb = col0 + wn * 32 + (lane & 3) * 2;

    if (col0 >= 1024 && col0 < 2048) {
        // ---- fused K L2-normalize: head = 64 cols = warp pair (wn & ~1) ----
        float* sspart = (float*)(sm + 2 * 36864);   // [4 wn][128 rows]
#pragma unroll
        for (int mi = 0; mi < 4; ++mi) {
            float s0 = 0.f, s1 = 0.f;
#pragma unroll
            for (int ni = 0; ni < 4; ++ni) {
                s0 = fmaf(acc[mi][ni][0], acc[mi][ni][0], s0);
                s0 = fmaf(acc[mi][ni][1], acc[mi][ni][1], s0);
                s1 = fmaf(acc[mi][ni][2], acc[mi][ni][2], s1);
                s1 = fmaf(acc[mi][ni][3], acc[mi][ni][3], s1);
            }
            s0 += __shfl_xor_sync(~0u, s0, 1);
            s0 += __shfl_xor_sync(~0u, s0, 2);
            s1 += __shfl_xor_sync(~0u, s1, 1);
            s1 += __shfl_xor_sync(~0u, s1, 2);
            if ((lane & 3) == 0) {
                int r0 = wm * 64 + mi * 16 + (lane >> 2);
                sspart[wn * 128 + r0] = s0;
                sspart[wn * 128 + r0 + 8] = s1;
            }
        }
        __syncthreads();
        const int base = (wn & 2) * 128;   // head's warp-pair base
#pragma unroll
        for (int mi = 0; mi < 4; ++mi) {
            int r0 = wm * 64 + mi * 16 + (lane >> 2);
            float ss0 = sspart[base + r0] + sspart[base + 128 + r0];
            float ss1 = sspart[base + r0 + 8] + sspart[base + 128 + r0 + 8];
            float inv0 = 1.f / fmaxf(sqrtf(ss0), 1e-12f);
            float inv1 = 1.f / fmaxf(sqrtf(ss1), 1e-12f);
#pragma unroll
            for (int ni = 0; ni < 4; ++ni) {
                int r = rb + mi * 16, cc = cb + ni * 8;
                *(float2*)(C + (size_t)r * ldc + cc) =
                    make_float2(acc[mi][ni][0] * inv0, acc[mi][ni][1] * inv0);
                *(float2*)(C + (size_t)(r + 8) * ldc + cc) =
                    make_float2(acc[mi][ni][2] * inv1, acc[mi][ni][3] * inv1);
            }
        }
    } else {
#pragma unroll
        for (int mi = 0; mi < 4; ++mi)
#pragma unroll
            for (int ni = 0; ni < 4; ++ni) {
                int r = rb + mi * 16, cc = cb + ni * 8;
                *(float2*)(C + (size_t)r * ldc + cc) =
                    make_float2(acc[mi][ni][0], acc[mi][ni][1]);
                *(float2*)(C + (size_t)(r + 8) * ldc + cc) =
                    make_float2(acc[mi][ni][2], acc[mi][ni][3]);
            }
    }
}

// ---------------------------------------------------------------------------
// fp32 -> fp16 flat cast
// ---------------------------------------------------------------------------
__global__ __launch_bounds__(256) void convert16(const float* __restrict__ in,
                                                 __half* __restrict__ out) {
    size_t i = (size_t)blockIdx.x * 256 + threadIdx.x;
    float4 v = ((const float4*)in)[i];
    __half2 a = __halves2half2(__float2half(v.x), __float2half(v.y));
    __half2 b = __halves2half2(__float2half(v.z), __float2half(v.w));
    __half2* o = (__half2*)out + i * 2;
    o[0] = a;
    o[1] = b;
}

// 4x W[1024][1024] fp32 -> Wt[n][1024] fp16 (transposed, K-major), one launch
__global__ __launch_bounds__(256) void transpose16x4(
    const float* __restrict__ W0, const float* __restrict__ W1,
    const float* __restrict__ W2, const float* __restrict__ W3,
    __half* __restrict__ o0, __half* __restrict__ o1,
    __half* __restrict__ o2, __half* __restrict__ o3) {
    const int z = blockIdx.z;
    const float* W = (z == 0) ? W0 : (z == 1) ? W1 : (z == 2) ? W2 : W3;
    __half* out = (z == 0) ? o0 : (z == 1) ? o1 : (z == 2) ? o2 : o3;
    __shared__ float s[32][33];
    const int tx = threadIdx.x & 31, ty = threadIdx.x >> 5;
    const int k0 = blockIdx.y << 5, n0 = blockIdx.x << 5;
#pragma unroll
    for (int r = 0; r < 32; r += 8)
        s[ty + r][tx] = W[(size_t)(k0 + ty + r) * 1024 + n0 + tx];
    __syncthreads();
#pragma unroll
    for (int r = 0; r < 32; r += 8) {
        const int n = n0 + ty + r, k = k0 + tx;
        out[(size_t)n * KP + k] = __float2half(s[tx][ty + r]);
    }
}

// Wa/Wb [1024][16] -> Wt32[32][1024] fp32
__global__ __launch_bounds__(256) void gates_prep32(const float* __restrict__ Wa,
                                                    const float* __restrict__ Wb,
                                                    float* __restrict__ out) {
    const int o = blockIdx.x;
    const float* W = (o < 16) ? Wa : Wb;
    const int h = o & 15;
    for (int k = threadIdx.x; k < 1024; k += 256)
        out[(size_t)o * 1024 + k] = W[k * 16 + h];
}

// ---------------------------------------------------------------------------
// Gates: logits = x @ Wt32^T, + bias, sigmoid. Block = 64 rows x 32 outputs.
// ---------------------------------------------------------------------------
__global__ __launch_bounds__(256) void gates64(const float* __restrict__ x,
                                               const float* __restrict__ Wt,
                                               const float* __restrict__ ba,
                                               const float* __restrict__ bb,
                                               float* __restrict__ alpha,
                                               float* __restrict__ beta) {
    __shared__ float xs[64][64];
    __shared__ float ws[32][65];
    const int tid = threadIdx.x;
    const int row0 = blockIdx.x * 64;
    const int rg = tid >> 5;
    const int o = tid & 31;

    float acc[8];
#pragma unroll
    for (int p = 0; p < 8; ++p) acc[p] = 0.f;

    for (int kc = 0; kc < 16; ++kc) {
        __syncthreads();
#pragma unroll
        for (int l = 0; l < 4; ++l) {
            int idx = tid + (l << 8);
            int r = idx >> 4, q = idx & 15;
            float4 v = *(const float4*)(x + (size_t)(row0 + r) * 1024 + kc * 64 + q * 4);
            *(float4*)(&xs[r][q * 4]) = v;
        }
#pragma unroll
        for (int l = 0; l < 2; ++l) {
            int idx = tid + (l << 8);
            int r = idx >> 4, q = idx & 15;
            float4 v = *(const float4*)(Wt + (size_t)r * 1024 + kc * 64 + q * 4);
            ws[r][q * 4 + 0] = v.x; ws[r][q * 4 + 1] = v.y;
            ws[r][q * 4 + 2] = v.z; ws[r][q * 4 + 3] = v.w;
        }
        __syncthreads();
#pragma unroll 8
        for (int k = 0; k < 64; ++k) {
            float wv = ws[o][k];
#pragma unroll
            for (int p = 0; p < 8; ++p)
                acc[p] = fmaf(xs[rg * 8 + p][k], wv, acc[p]);
        }
    }

    const float bias = (o < 16) ? ba[o] : bb[o - 16];
#pragma unroll
    for (int p = 0; p < 8; ++p) {
        float r = 1.f / (1.f + expf(-(acc[p] + bias)));
        int row = row0 + rg * 8 + p;
        if (o < 16) alpha[(size_t)row * 16 + o] = r;
        else        beta[(size_t)row * 16 + (o - 16)] = r;
    }
}

// ---------------------------------------------------------------------------
// Sequential scan v4: as v3 (128 blocks, 256 threads, 8 cols/thread) but the
// inner step uses packed f32x2 math (mul.rn.f32x2 / fma.rn.f32x2, sm_100+
// base ISA): 12 packed ops/step vs 24 scalar. Per-lane rounding identical;
// dot reassociates (2 parallel partials) — ~1e-7 effect.
// ---------------------------------------------------------------------------
__global__ __launch_bounds__(256) void scan_kernel4(
    const float* __restrict__ QKV, const float* __restrict__ alpha,
    const float* __restrict__ beta, const float* __restrict__ S0,
    __half* __restrict__ Y2, float* __restrict__ Sout) {
    constexpr int CH = 16;
    __shared__ float cq[2][CH][64];
    __shared__ float ck[2][CH][64];
    __shared__ float cv[2][CH][32];
    __shared__ float ca[2][CH];
    __shared__ float cb[2][CH];

    const int tid = threadIdx.x;
    const int bh2 = blockIdx.x;          // 0..127
    const int bh = bh2 >> 1, half = bh2 & 1;
    const int b = bh >> 4, h = bh & 15;
    const int i = tid >> 3;              // row 0..31
    const int gi = half * 32 + i;        // row 0..63
    const int jg = tid & 7;              // col group
    const int j0 = jg << 3;              // 8 cols

    unsigned long long s2[4];            // 8 state floats as 4 f32x2
    {
        const unsigned long long* sp =
            (const unsigned long long*)(S0 + ((size_t)bh * 64 + gi) * 64 + j0);
        s2[0] = sp[0]; s2[1] = sp[1]; s2[2] = sp[2]; s2[3] = sp[3];
    }

    const float* rowQ = QKV + (size_t)b * T_ * 3072 + (size_t)h * 64;

    auto load_chunk = [&](int t0, int buf) {
        {
            int st = tid >> 4, f = (tid & 15) << 2;
            const float* base = rowQ + (size_t)(t0 + st) * 3072;
            *(float4*)(&cq[buf][st][f]) = *(const float4*)(base + f);
            *(float4*)(&ck[buf][st][f]) = *(const float4*)(base + 1024 + f);
        }
        if (tid < 128) {
            int st = tid >> 3, f = (tid & 7) << 2;
            const float* base = rowQ + (size_t)(t0 + st) * 3072 + 2048 + half * 32;
            *(float4*)(&cv[buf][st][f]) = *(const float4*)(base + f);
        }
        if (tid < CH)
            ca[buf][tid] = alpha[((size_t)b * T_ + t0 + tid) * H_ + h];
        else if (tid < 2 * CH)
            cb[buf][tid - CH] = beta[((size_t)b * T_ + t0 + tid - CH) * H_ + h];
    };

    const size_t ybase = (size_t)b * T_ * KP + (size_t)h * 64 + gi;
    const int nch = T_ / CH;
    load_chunk(0, 0);
    __syncthreads();

    for (int c = 0; c < nch; ++c) {
        const int buf = c & 1;
        if (c + 1 < nch) load_chunk((c + 1) * CH, buf ^ 1);

#pragma unroll 4
        for (int s = 0; s < CH; ++s) {
            const float a = ca[buf][s];
            const float bv = cb[buf][s] * cv[buf][s][i];
            unsigned long long a2, bv2, p2;
            asm("mov.b64 %0, {%1, %1};" : "=l"(a2) : "f"(a));
            asm("mov.b64 %0, {%1, %1};" : "=l"(bv2) : "f"(bv));
            asm("mov.b64 %0, {%1, %1};" : "=l"(p2) : "f"(0.f));
            const unsigned long long* kp =
                (const unsigned long long*)(&ck[buf][s][j0]);
            const unsigned long long* qp =
                (const unsigned long long*)(&cq[buf][s][j0]);
#pragma unroll
            for (int v = 0; v < 4; ++v) {
                unsigned long long k2 = kp[v], q2 = qp[v], t;
                asm("mul.rn.f32x2 %0, %1, %2;" : "=l"(t) : "l"(bv2), "l"(k2));
                asm("fma.rn.f32x2 %0, %1, %0, %2;" : "+l"(s2[v]) : "l"(a2), "l"(t));
                asm("fma.rn.f32x2 %0, %1, %2, %0;" : "+l"(p2) : "l"(s2[v]), "l"(q2));
            }
            float plo, phi;
            asm("mov.b64 {%0, %1}, %2;" : "=f"(plo), "=f"(phi) : "l"(p2));
            float partial = plo + phi;
            partial += __shfl_xor_sync(~0u, partial, 1);
            partial += __shfl_xor_sync(~0u, partial, 2);
            partial += __shfl_xor_sync(~0u, partial, 4);
            if (jg == 0)
                Y2[ybase + (size_t)(c * CH + s) * KP] = __float2half(partial);
        }
        __syncthreads();
    }

    unsigned long long* so =
        (unsigned long long*)(Sout + ((size_t)bh * 64 + gi) * 64 + j0);
    so[0] = s2[0]; so[1] = s2[1]; so[2] = s2[2]; so[3] = s2[3];
}

// ---------------------------------------------------------------------------
extern "C" void kernel_launch(void* const* d_in, const int* in_sizes, int n_in,
                              void* d_out, int out_size) {
    (void)in_sizes; (void)n_in;
    const float* x  = (const float*)d_in[0];
    const float* S0 = (const float*)d_in[1];
    const float* Wq = (const float*)d_in[2];
    const float* Wk = (const float*)d_in[3];
    const float* Wv = (const float*)d_in[4];
    const float* Wa = (const float*)d_in[5];
    const float* ba = (const float*)d_in[6];
    const float* Wb = (const float*)d_in[7];
    const float* bb = (const float*)d_in[8];
    const float* Wo = (const float*)d_in[9];
    float* out = (float*)d_out;

    float *QKVd, *al, *be, *Sdump, *Wab32;
    __half *A2, *Y2, *Wqkv, *Wto;
    cudaGetSymbolAddress((void**)&QKVd, g_QKV);
    cudaGetSymbolAddress((void**)&al, g_alpha);
    cudaGetSymbolAddress((void**)&be, g_beta);
    cudaGetSymbolAddress((void**)&Sdump, g_Sdump);
    cudaGetSymbolAddress((void**)&Wab32, g_Wab32);
    cudaGetSymbolAddress((void**)&A2, g_A2);
    cudaGetSymbolAddress((void**)&Y2, g_Y2);
    cudaGetSymbolAddress((void**)&Wqkv, g_Wqkv);
    cudaGetSymbolAddress((void**)&Wto, g_Wto);

    float* Sout = (out_size >= NROWS * DM_ + STATE_ELEMS) ? out + (size_t)NROWS * DM_ : Sdump;

    constexpr int GSMEM = 2 * 36864 + 4 * 128 * 4;   // stages + knorm partials = 75776
    cudaFuncSetAttribute(gemm_mma, cudaFuncAttributeMaxDynamicSharedMemorySize, GSMEM);

    convert16<<<NROWS, 256>>>(x, A2);
    transpose16x4<<<dim3(32, 32, 4), 256>>>(Wq, Wk, Wv, Wo,
                                            Wqkv,
                                            Wqkv + (size_t)1024 * KP,
                                            Wqkv + (size_t)2048 * KP,
                                            Wto);
    gates_prep32<<<32, 256>>>(Wa, Wb, Wab32);
    gemm_mma<<<dim3(3072 / 128, NROWS / 128), 256, GSMEM>>>(A2, Wqkv, QKVd, 3072);  // + fused knorm
    gates64<<<NROWS / 64, 256>>>(x, Wab32, ba, bb, al, be);
    scan_kernel4<<<128, 256>>>(QKVd, al, be, S0, Y2, Sout);
    gemm_mma<<<dim3(1024 / 128, NROWS / 128), 256, GSMEM>>>(Y2, Wto, out, 1024);
}

// round 17
// speedup vs baseline: 1.0060x; 1.0012x over previous
#include <cuda_runtime.h>
#include <cuda_fp16.h>
#include <cstdint>
#include <math.h>

// Problem dims
constexpr int B_ = 4, T_ = 2048, DM_ = 1024, H_ = 16, D_ = 64;
constexpr int NROWS = B_ * T_;           // 8192
constexpr int KP = 1024;                 // plain fp16 GEMM (no split)
constexpr int STATE_ELEMS = B_ * H_ * D_ * D_;

// ---------------- scratch (device globals; allocation-free) ----------------
__device__ float g_QKV[(size_t)NROWS * 3072];   // fused Q|K|V fp32
__device__ float g_alpha[NROWS * H_];
__device__ float g_beta[NROWS * H_];
__device__ float g_Sdump[STATE_ELEMS];
__device__ float g_Wab32[32 * DM_];
__device__ __half g_A2[(size_t)NROWS * KP];
__device__ __half g_Y2[(size_t)NROWS * KP];     // scan writes fp16 directly
__device__ __half g_Wqkv[(size_t)3072 * KP];    // rows: Wq|Wk|Wv output cols
__device__ __half g_Wto[(size_t)DM_ * KP];

// ---------------------------------------------------------------------------
// fp16 mma.sync GEMM — EXACT R14 config (proven 690.9us): CTA 128x128,
// 8 warps (2M x 4N), warp tile 64x32, Kc=64, double-buffered cp.async,
// 2 CTAs/SM, pad-72 smem. Fused K-normalize epilogue for col0 in [1024,2048).
// ---------------------------------------------------------------------------
__global__ __launch_bounds__(256, 2) void gemm_mma(const __half* __restrict__ A,
                                                   const __half* __restrict__ Bw,
                                                   float* __restrict__ C, int ldc) {
    extern __shared__ char sm[];
    const int tid = threadIdx.x;
    const int lane = tid & 31, wid = tid >> 5;
    const int wm = wid & 1, wn = wid >> 1;       // 2 x 4 warp grid
    const int row0 = blockIdx.y * 128;
    const int col0 = blockIdx.x * 128;

    uint32_t sb;
    asm("{ .reg .u64 t; cvta.to.shared.u64 t, %1; cvt.u32.u64 %0, t; }" : "=r"(sb) : "l"(sm));

    const uint32_t A_OFF[2] = {0u, 36864u};
    const uint32_t B_OFF[2] = {18432u, 36864u + 18432u};

    float acc[4][4][4];
#pragma unroll
    for (int i = 0; i < 4; ++i)
#pragma unroll
        for (int j = 0; j < 4; ++j)
#pragma unroll
            for (int q = 0; q < 4; ++q) acc[i][j][q] = 0.f;

    auto load_chunk = [&](int c, int buf) {
        const __half* gA = A + (size_t)row0 * KP + c * 64;
        uint32_t ab = sb + A_OFF[buf];
#pragma unroll
        for (int l = 0; l < 4; ++l) {
            int idx = tid + (l << 8);
            int r = idx >> 3, s = idx & 7;
            uint32_t so = ab + (uint32_t)(r * 144 + s * 16);
            const void* gp = gA + (size_t)r * KP + s * 8;
            asm volatile("cp.async.cg.shared.global [%0], [%1], 16;" :: "r"(so), "l"(gp));
        }
        const __half* gB = Bw + (size_t)col0 * KP + c * 64;
        uint32_t bbx = sb + B_OFF[buf];
#pragma unroll
        for (int l = 0; l < 4; ++l) {
            int idx = tid + (l << 8);
            int n = idx >> 3, s = idx & 7;
            uint32_t so = bbx + (uint32_t)(n * 144 + s * 16);
            const void* gp = gB + (size_t)n * KP + s * 8;
            asm volatile("cp.async.cg.shared.global [%0], [%1], 16;" :: "r"(so), "l"(gp));
        }
        asm volatile("cp.async.commit_group;" ::: "memory");
    };

    const uint32_t a_base = (uint32_t)((wm * 64 + (lane & 15)) * 72 + ((lane >> 4) << 3));
    const uint32_t b_base = (uint32_t)((wn * 32 + (((lane >> 4) & 1) << 3) + (lane & 7)) * 72 +
                                       (((lane >> 3) & 1) << 3));

    load_chunk(0, 0);

    constexpr int NCH = KP / 64;  // 16
    for (int c = 0; c < NCH; ++c) {
        const int buf = c & 1;
        if (c + 1 < NCH) {
            load_chunk(c + 1, buf ^ 1);
            asm volatile("cp.async.wait_group 1;" ::: "memory");
        } else {
            asm volatile("cp.async.wait_group 0;" ::: "memory");
        }
        __syncthreads();

        const uint32_t ab = sb + A_OFF[buf];
        const uint32_t bbs = sb + B_OFF[buf];
#pragma unroll
        for (int ks = 0; ks < 4; ++ks) {
            uint32_t af[4][4];
#pragma unroll
            for (int mi = 0; mi < 4; ++mi) {
                uint32_t addr = ab + (a_base + (uint32_t)(mi * 16 * 72 + ks * 16)) * 2;
                asm volatile("ldmatrix.sync.aligned.m8n8.x4.shared.b16 {%0,%1,%2,%3}, [%4];"
                             : "=r"(af[mi][0]), "=r"(af[mi][1]), "=r"(af[mi][2]), "=r"(af[mi][3])
                             : "r"(addr));
            }
            uint32_t bf[4][2];
#pragma unroll
            for (int nb = 0; nb < 2; ++nb) {
                uint32_t addr = bbs + (b_base + (uint32_t)(nb * 16 * 72 + ks * 16)) * 2;
                asm volatile("ldmatrix.sync.aligned.m8n8.x4.shared.b16 {%0,%1,%2,%3}, [%4];"
                             : "=r"(bf[2 * nb][0]), "=r"(bf[2 * nb][1]),
                               "=r"(bf[2 * nb + 1][0]), "=r"(bf[2 * nb + 1][1])
                             : "r"(addr));
            }
#pragma unroll
            for (int mi = 0; mi < 4; ++mi)
#pragma unroll
                for (int ni = 0; ni < 4; ++ni) {
                    asm volatile(
                        "mma.sync.aligned.m16n8k16.row.col.f32.f16.f16.f32 "
                        "{%0,%1,%2,%3}, {%4,%5,%6,%7}, {%8,%9}, {%0,%1,%2,%3};"
                        : "+f"(acc[mi][ni][0]), "+f"(acc[mi][ni][1]),
                          "+f"(acc[mi][ni][2]), "+f"(acc[mi][ni][3])
                        : "r"(af[mi][0]), "r"(af[mi][1]), "r"(af[mi][2]), "r"(af[mi][3]),
                          "r"(bf[ni][0]), "r"(bf[ni][1]));
                }
        }
        __syncthreads();
    }

    const int rb = row0 + wm * 64 + (lane >> 2);
    const int cb = col0 + wn * 32 + (lane & 3) * 2;

    if (col0 >= 1024 && col0 < 2048) {
        // ---- fused K L2-normalize: head = 64 cols = warp pair (wn & ~1) ----
        float* sspart = (float*)(sm + 2 * 36864);   // [4 wn][128 rows]
#pragma unroll
        for (int mi = 0; mi < 4; ++mi) {
            float s0 = 0.f, s1 = 0.f;
#pragma unroll
            for (int ni = 0; ni < 4; ++ni) {
                s0 = fmaf(acc[mi][ni][0], acc[mi][ni][0], s0);
                s0 = fmaf(acc[mi][ni][1], acc[mi][ni][1], s0);
                s1 = fmaf(acc[mi][ni][2], acc[mi][ni][2], s1);
                s1 = fmaf(acc[mi][ni][3], acc[mi][ni][3], s1);
            }
            s0 += __shfl_xor_sync(~0u, s0, 1);
            s0 += __shfl_xor_sync(~0u, s0, 2);
            s1 += __shfl_xor_sync(~0u, s1, 1);
            s1 += __shfl_xor_sync(~0u, s1, 2);
            if ((lane & 3) == 0) {
                int r0 = wm * 64 + mi * 16 + (lane >> 2);
                sspart[wn * 128 + r0] = s0;
                sspart[wn * 128 + r0 + 8] = s1;
            }
        }
        __syncthreads();
        const int base = (wn & 2) * 128;   // head's warp-pair base
#pragma unroll
        for (int mi = 0; mi < 4; ++mi) {
            int r0 = wm * 64 + mi * 16 + (lane >> 2);
            float ss0 = sspart[base + r0] + sspart[base + 128 + r0];
            float ss1 = sspart[base + r0 + 8] + sspart[base + 128 + r0 + 8];
            float inv0 = 1.f / fmaxf(sqrtf(ss0), 1e-12f);
            float inv1 = 1.f / fmaxf(sqrtf(ss1), 1e-12f);
#pragma unroll
            for (int ni = 0; ni < 4; ++ni) {
                int r = rb + mi * 16, cc = cb + ni * 8;
                *(float2*)(C + (size_t)r * ldc + cc) =
                    make_float2(acc[mi][ni][0] * inv0, acc[mi][ni][1] * inv0);
                *(float2*)(C + (size_t)(r + 8) * ldc + cc) =
                    make_float2(acc[mi][ni][2] * inv1, acc[mi][ni][3] * inv1);
            }
        }
    } else {
#pragma unroll
        for (int mi = 0; mi < 4; ++mi)
#pragma unroll
            for (int ni = 0; ni < 4; ++ni) {
                int r = rb + mi * 16, cc = cb + ni * 8;
                *(float2*)(C + (size_t)r * ldc + cc) =
                    make_float2(acc[mi][ni][0], acc[mi][ni][1]);
                *(float2*)(C + (size_t)(r + 8) * ldc + cc) =
                    make_float2(acc[mi][ni][2], acc[mi][ni][3]);
            }
    }
}

// ---------------------------------------------------------------------------
// fp32 -> fp16 flat cast
// ---------------------------------------------------------------------------
__global__ __launch_bounds__(256) void convert16(const float* __restrict__ in,
                                                 __half* __restrict__ out) {
    size_t i = (size_t)blockIdx.x * 256 + threadIdx.x;
    float4 v = ((const float4*)in)[i];
    __half2 a = __halves2half2(__float2half(v.x), __float2half(v.y));
    __half2 b = __halves2half2(__float2half(v.z), __float2half(v.w));
    __half2* o = (__half2*)out + i * 2;
    o[0] = a;
    o[1] = b;
}

// 4x W[1024][1024] fp32 -> Wt[n][1024] fp16 (transposed, K-major), one launch
__global__ __launch_bounds__(256) void transpose16x4(
    const float* __restrict__ W0, const float* __restrict__ W1,
    const float* __restrict__ W2, const float* __restrict__ W3,
    __half* __restrict__ o0, __half* __restrict__ o1,
    __half* __restrict__ o2, __half* __restrict__ o3) {
    const int z = blockIdx.z;
    const float* W = (z == 0) ? W0 : (z == 1) ? W1 : (z == 2) ? W2 : W3;
    __half* out = (z == 0) ? o0 : (z == 1) ? o1 : (z == 2) ? o2 : o3;
    __shared__ float s[32][33];
    const int tx = threadIdx.x & 31, ty = threadIdx.x >> 5;
    const int k0 = blockIdx.y << 5, n0 = blockIdx.x << 5;
#pragma unroll
    for (int r = 0; r < 32; r += 8)
        s[ty + r][tx] = W[(size_t)(k0 + ty + r) * 1024 + n0 + tx];
    __syncthreads();
#pragma unroll
    for (int r = 0; r < 32; r += 8) {
        const int n = n0 + ty + r, k = k0 + tx;
        out[(size_t)n * KP + k] = __float2half(s[tx][ty + r]);
    }
}

// Wa/Wb [1024][16] -> Wt32[32][1024] fp32
__global__ __launch_bounds__(256) void gates_prep32(const float* __restrict__ Wa,
                                                    const float* __restrict__ Wb,
                                                    float* __restrict__ out) {
    const int o = blockIdx.x;
    const float* W = (o < 16) ? Wa : Wb;
    const int h = o & 15;
    for (int k = threadIdx.x; k < 1024; k += 256)
        out[(size_t)o * 1024 + k] = W[k * 16 + h];
}

// ---------------------------------------------------------------------------
// Gates: logits = x @ Wt32^T, + bias, sigmoid. Block = 64 rows x 32 outputs.
// ---------------------------------------------------------------------------
__global__ __launch_bounds__(256) void gates64(const float* __restrict__ x,
                                               const float* __restrict__ Wt,
                                               const float* __restrict__ ba,
                                               const float* __restrict__ bb,
                                               float* __restrict__ alpha,
                                               float* __restrict__ beta) {
    __shared__ float xs[64][64];
    __shared__ float ws[32][65];
    const int tid = threadIdx.x;
    const int row0 = blockIdx.x * 64;
    const int rg = tid >> 5;
    const int o = tid & 31;

    float acc[8];
#pragma unroll
    for (int p = 0; p < 8; ++p) acc[p] = 0.f;

    for (int kc = 0; kc < 16; ++kc) {
        __syncthreads();
#pragma unroll
        for (int l = 0; l < 4; ++l) {
            int idx = tid + (l << 8);
            int r = idx >> 4, q = idx & 15;
            float4 v = *(const float4*)(x + (size_t)(row0 + r) * 1024 + kc * 64 + q * 4);
            *(float4*)(&xs[r][q * 4]) = v;
        }
#pragma unroll
        for (int l = 0; l < 2; ++l) {
            int idx = tid + (l << 8);
            int r = idx >> 4, q = idx & 15;
            float4 v = *(const float4*)(Wt + (size_t)r * 1024 + kc * 64 + q * 4);
            ws[r][q * 4 + 0] = v.x; ws[r][q * 4 + 1] = v.y;
            ws[r][q * 4 + 2] = v.z; ws[r][q * 4 + 3] = v.w;
        }
        __syncthreads();
#pragma unroll 8
        for (int k = 0; k < 64; ++k) {
            float wv = ws[o][k];
#pragma unroll
            for (int p = 0; p < 8; ++p)
                acc[p] = fmaf(xs[rg * 8 + p][k], wv, acc[p]);
        }
    }

    const float bias = (o < 16) ? ba[o] : bb[o - 16];
#pragma unroll
    for (int p = 0; p < 8; ++p) {
        float r = 1.f / (1.f + expf(-(acc[p] + bias)));
        int row = row0 + rg * 8 + p;
        if (o < 16) alpha[(size_t)row * 16 + o] = r;
        else        beta[(size_t)row * 16 + (o - 16)] = r;
    }
}

// ---------------------------------------------------------------------------
// Sequential scan v3 (R13/R14-proven): 128 blocks, 256 threads; thread owns
// row i (of 32) and 8 cols; 8-lane xor-shfl reduction; writes fp16 Y2.
// ---------------------------------------------------------------------------
__global__ __launch_bounds__(256) void scan_kernel3(
    const float* __restrict__ QKV, const float* __restrict__ alpha,
    const float* __restrict__ beta, const float* __restrict__ S0,
    __half* __restrict__ Y2, float* __restrict__ Sout) {
    constexpr int CH = 16;
    __shared__ float cq[2][CH][64];
    __shared__ float ck[2][CH][64];
    __shared__ float cv[2][CH][32];
    __shared__ float ca[2][CH];
    __shared__ float cb[2][CH];

    const int tid = threadIdx.x;
    const int bh2 = blockIdx.x;          // 0..127
    const int bh = bh2 >> 1, half = bh2 & 1;
    const int b = bh >> 4, h = bh & 15;
    const int i = tid >> 3;              // row 0..31
    const int gi = half * 32 + i;        // row 0..63
    const int jg = tid & 7;              // col group
    const int j0 = jg << 3;              // 8 cols

    float4 s4[2];
    {
        const float4* sp = (const float4*)(S0 + ((size_t)bh * 64 + gi) * 64 + j0);
        s4[0] = sp[0]; s4[1] = sp[1];
    }

    const float* rowQ = QKV + (size_t)b * T_ * 3072 + (size_t)h * 64;

    auto load_chunk = [&](int t0, int buf) {
        {
            int st = tid >> 4, f = (tid & 15) << 2;
            const float* base = rowQ + (size_t)(t0 + st) * 3072;
            *(float4*)(&cq[buf][st][f]) = *(const float4*)(base + f);
            *(float4*)(&ck[buf][st][f]) = *(const float4*)(base + 1024 + f);
        }
        if (tid < 128) {
            int st = tid >> 3, f = (tid & 7) << 2;
            const float* base = rowQ + (size_t)(t0 + st) * 3072 + 2048 + half * 32;
            *(float4*)(&cv[buf][st][f]) = *(const float4*)(base + f);
        }
        if (tid < CH)
            ca[buf][tid] = alpha[((size_t)b * T_ + t0 + tid) * H_ + h];
        else if (tid < 2 * CH)
            cb[buf][tid - CH] = beta[((size_t)b * T_ + t0 + tid - CH) * H_ + h];
    };

    const size_t ybase = (size_t)b * T_ * KP + (size_t)h * 64 + gi;
    const int nch = T_ / CH;
    load_chunk(0, 0);
    __syncthreads();

    for (int c = 0; c < nch; ++c) {
        const int buf = c & 1;
        if (c + 1 < nch) load_chunk((c + 1) * CH, buf ^ 1);

#pragma unroll 4
        for (int s = 0; s < CH; ++s) {
            const float a = ca[buf][s];
            const float bg = cb[buf][s];
            const float bv = bg * cv[buf][s][i];
            const float4* kp = (const float4*)(&ck[buf][s][j0]);
            const float4* qp = (const float4*)(&cq[buf][s][j0]);
            float partial = 0.f;
#pragma unroll
            for (int v = 0; v < 2; ++v) {
                float4 kk = kp[v];
                float4 qq = qp[v];
                s4[v].x = fmaf(a, s4[v].x, bv * kk.x); partial = fmaf(s4[v].x, qq.x, partial);
                s4[v].y = fmaf(a, s4[v].y, bv * kk.y); partial = fmaf(s4[v].y, qq.y, partial);
                s4[v].z = fmaf(a, s4[v].z, bv * kk.z); partial = fmaf(s4[v].z, qq.z, partial);
                s4[v].w = fmaf(a, s4[v].w, bv * kk.w); partial = fmaf(s4[v].w, qq.w, partial);
            }
            partial += __shfl_xor_sync(~0u, partial, 1);
            partial += __shfl_xor_sync(~0u, partial, 2);
            partial += __shfl_xor_sync(~0u, partial, 4);
            if (jg == 0)
                Y2[ybase + (size_t)(c * CH + s) * KP] = __float2half(partial);
        }
        __syncthreads();
    }

    float4* so = (float4*)(Sout + ((size_t)bh * 64 + gi) * 64 + j0);
    so[0] = s4[0]; so[1] = s4[1];
}

// ---------------------------------------------------------------------------
extern "C" void kernel_launch(void* const* d_in, const int* in_sizes, int n_in,
                              void* d_out, int out_size) {
    (void)in_sizes; (void)n_in;
    const float* x  = (const float*)d_in[0];
    const float* S0 = (const float*)d_in[1];
    const float* Wq = (const float*)d_in[2];
    const float* Wk = (const float*)d_in[3];
    const float* Wv = (const float*)d_in[4];
    const float* Wa = (const float*)d_in[5];
    const float* ba = (const float*)d_in[6];
    const float* Wb = (const float*)d_in[7];
    const float* bb = (const float*)d_in[8];
    const float* Wo = (const float*)d_in[9];
    float* out = (float*)d_out;

    float *QKVd, *al, *be, *Sdump, *Wab32;
    __half *A2, *Y2, *Wqkv, *Wto;
    cudaGetSymbolAddress((void**)&QKVd, g_QKV);
    cudaGetSymbolAddress((void**)&al, g_alpha);
    cudaGetSymbolAddress((void**)&be, g_beta);
    cudaGetSymbolAddress((void**)&Sdump, g_Sdump);
    cudaGetSymbolAddress((void**)&Wab32, g_Wab32);
    cudaGetSymbolAddress((void**)&A2, g_A2);
    cudaGetSymbolAddress((void**)&Y2, g_Y2);
    cudaGetSymbolAddress((void**)&Wqkv, g_Wqkv);
    cudaGetSymbolAddress((void**)&Wto, g_Wto);

    float* Sout = (out_size >= NROWS * DM_ + STATE_ELEMS) ? out + (size_t)NROWS * DM_ : Sdump;

    constexpr int GSMEM = 2 * 36864 + 4 * 128 * 4;   // stages + knorm partials = 75776
    cudaFuncSetAttribute(gemm_mma, cudaFuncAttributeMaxDynamicSharedMemorySize, GSMEM);

    // Side streams + events, created once on the first (uncaptured) call.
    // During graph capture these form a fork/join DAG (standard capture
    // pattern): both side streams rejoin the origin stream before capture end.
    static cudaStream_t s1 = nullptr, s2 = nullptr;
    static cudaEvent_t ev0 = nullptr, ev1 = nullptr, ev2 = nullptr;
    if (s1 == nullptr) {
        cudaStreamCreateWithFlags(&s1, cudaStreamNonBlocking);
        cudaStreamCreateWithFlags(&s2, cudaStreamNonBlocking);
        cudaEventCreateWithFlags(&ev0, cudaEventDisableTiming);
        cudaEventCreateWithFlags(&ev1, cudaEventDisableTiming);
        cudaEventCreateWithFlags(&ev2, cudaEventDisableTiming);
    }

    // fork
    cudaEventRecord(ev0, 0);
    cudaStreamWaitEvent(s1, ev0, 0);
    cudaStreamWaitEvent(s2, ev0, 0);

    // branch s1: weight transposes
    transpose16x4<<<dim3(32, 32, 4), 256, 0, s1>>>(Wq, Wk, Wv, Wo,
                                                   Wqkv,
                                                   Wqkv + (size_t)1024 * KP,
                                                   Wqkv + (size_t)2048 * KP,
                                                   Wto);
    cudaEventRecord(ev1, s1);

    // branch s2: gate weights + gate GEMM (depends only on x)
    gates_prep32<<<32, 256, 0, s2>>>(Wa, Wb, Wab32);
    gates64<<<NROWS / 64, 256, 0, s2>>>(x, Wab32, ba, bb, al, be);
    cudaEventRecord(ev2, s2);

    // main stream
    convert16<<<NROWS, 256>>>(x, A2);
    cudaStreamWaitEvent(0, ev1, 0);    // Wqkv/Wto ready
    gemm_mma<<<dim3(3072 / 128, NROWS / 128), 256, GSMEM>>>(A2, Wqkv, QKVd, 3072);  // + fused knorm
    cudaStreamWaitEvent(0, ev2, 0);    // alpha/beta ready
    scan_kernel3<<<128, 256>>>(QKVd, al, be, S0, Y2, Sout);
    gemm_mma<<<dim3(1024 / 128, NROWS / 128), 256, GSMEM>>>(Y2, Wto, out, 1024);
}